// round 6
// baseline (speedup 1.0000x reference)
#include <cuda_runtime.h>
#include <cstdint>

// PoolingLayer: out[p, f] = max_k features[idx[p,k], f]
// NP=50000, K=32, F=128. features: (100000,128) f32, L2-resident (51.2MB).
// idx: (50000,32) int32.
//
// 1 warp per output point; lane l owns float4 #l of the row (512B/row, fully
// coalesced). R5 showed L2=73.6% with regs capped at 32 (MLP/warp ~2).
// This version batches 8 independent float4 gathers per group (launch_bounds
// relaxed to 4 blocks/SM -> <=64 regs) to drive MLP/warp to 8 and saturate L2.

#define NP_POINTS 50000
#define N_POINTS  100000
#define K_NEIGH   32
#define F_VEC4    32   // 128 floats = 32 float4
#define BATCH     8

#define SZ_FEATURES 12800000   // 100000 * 128 f32
#define SZ_INDICES  1600000    // 50000 * 32

__global__ __launch_bounds__(256, 4)
void pool_max_kernel(const float4* __restrict__ feat,
                     const int* __restrict__ idx,
                     float4* __restrict__ out)
{
    const int gtid = blockIdx.x * blockDim.x + threadIdx.x;
    const int warp = gtid >> 5;
    const int lane = gtid & 31;
    if (warp >= NP_POINTS) return;

    // Coalesced, read-once index load.
    int my_idx = __ldcs(&idx[warp * K_NEIGH + lane]);
    // Clamp: a format surprise becomes rel_err, never an illegal access.
    my_idx = min(max(my_idx, 0), N_POINTS - 1);

    const float NEG_INF = -__int_as_float(0x7f800000);
    float4 m0 = make_float4(NEG_INF, NEG_INF, NEG_INF, NEG_INF);
    float4 m1 = m0;

    #pragma unroll
    for (int kb = 0; kb < K_NEIGH / BATCH; ++kb) {
        // Phase 1: issue 8 independent gathers (front-batched -> MLP=8).
        float4 v[BATCH];
        #pragma unroll
        for (int u = 0; u < BATCH; ++u) {
            const int j = __shfl_sync(0xffffffffu, my_idx, kb * BATCH + u);
            v[u] = __ldg(&feat[(long long)j * F_VEC4 + lane]);
        }
        // Phase 2: fold into two parallel accumulators (short dep chain).
        #pragma unroll
        for (int u = 0; u < BATCH; u += 2) {
            m0.x = fmaxf(m0.x, v[u].x);   m1.x = fmaxf(m1.x, v[u+1].x);
            m0.y = fmaxf(m0.y, v[u].y);   m1.y = fmaxf(m1.y, v[u+1].y);
            m0.z = fmaxf(m0.z, v[u].z);   m1.z = fmaxf(m1.z, v[u+1].z);
            m0.w = fmaxf(m0.w, v[u].w);   m1.w = fmaxf(m1.w, v[u+1].w);
        }
    }

    float4 m;
    m.x = fmaxf(m0.x, m1.x);
    m.y = fmaxf(m0.y, m1.y);
    m.z = fmaxf(m0.z, m1.z);
    m.w = fmaxf(m0.w, m1.w);

    // Write-once output: streaming store, don't pollute L2.
    __stcs(&out[(long long)warp * F_VEC4 + lane], m);
}

extern "C" void kernel_launch(void* const* d_in, const int* in_sizes, int n_in,
                              void* d_out, int out_size)
{
    // Resolve inputs by element count (order-independent):
    //   features : 12800000 f32
    //   indices  : 1600000 int32
    const float4* feat = nullptr;
    const int*    idx  = nullptr;
    for (int i = 0; i < n_in; ++i) {
        if (in_sizes[i] == SZ_FEATURES)     feat = (const float4*)d_in[i];
        else if (in_sizes[i] == SZ_INDICES) idx  = (const int*)d_in[i];
    }
    if (!feat) feat = (const float4*)d_in[1];
    if (!idx)  idx  = (const int*)d_in[2];

    float4* out = (float4*)d_out;

    const int total_threads = NP_POINTS * 32;   // one warp per point
    const int block = 256;
    const int grid = (total_threads + block - 1) / block;  // 6250
    pool_max_kernel<<<grid, block>>>(feat, idx, out);
}

// round 7
// speedup vs baseline: 1.4159x; 1.4159x over previous
#include <cuda_runtime.h>
#include <cstdint>

// PoolingLayer: out[p, f] = max_k features[idx[p,k], f]
// NP=50000, K=32, F=128. features: (100000,128) f32, mostly L2-resident.
// idx: (50000,32) int32.
//
// 1 warp per output point; lane l owns float4 #l of the row (512B/row, fully
// coalesced). R5 (occ 93%, MLP~2) = 45.1us; R6 (occ 43%, MLP 8) = 62us.
// This version: batch=4 at 6 blocks/SM (occ ~75%, MLP 4) — more outstanding
// loads per SM than R5 without the occupancy collapse of R6.

#define NP_POINTS 50000
#define N_POINTS  100000
#define K_NEIGH   32
#define F_VEC4    32   // 128 floats = 32 float4
#define BATCH     4

#define SZ_FEATURES 12800000   // 100000 * 128 f32
#define SZ_INDICES  1600000    // 50000 * 32

__global__ __launch_bounds__(256, 6)
void pool_max_kernel(const float4* __restrict__ feat,
                     const int* __restrict__ idx,
                     float4* __restrict__ out)
{
    const int gtid = blockIdx.x * blockDim.x + threadIdx.x;
    const int warp = gtid >> 5;
    const int lane = gtid & 31;
    if (warp >= NP_POINTS) return;

    // Coalesced, read-once index load.
    int my_idx = __ldcs(&idx[warp * K_NEIGH + lane]);
    // Clamp: a format surprise becomes rel_err, never an illegal access.
    my_idx = min(max(my_idx, 0), N_POINTS - 1);

    const float NEG_INF = -__int_as_float(0x7f800000);
    float4 m0 = make_float4(NEG_INF, NEG_INF, NEG_INF, NEG_INF);
    float4 m1 = m0;

    #pragma unroll
    for (int kb = 0; kb < K_NEIGH / BATCH; ++kb) {
        // Phase 1: issue 4 independent gathers (front-batched -> MLP=4).
        float4 v[BATCH];
        #pragma unroll
        for (int u = 0; u < BATCH; ++u) {
            const int j = __shfl_sync(0xffffffffu, my_idx, kb * BATCH + u);
            v[u] = __ldg(&feat[(long long)j * F_VEC4 + lane]);
        }
        // Phase 2: fold into two parallel accumulators (short dep chain).
        #pragma unroll
        for (int u = 0; u < BATCH; u += 2) {
            m0.x = fmaxf(m0.x, v[u].x);   m1.x = fmaxf(m1.x, v[u+1].x);
            m0.y = fmaxf(m0.y, v[u].y);   m1.y = fmaxf(m1.y, v[u+1].y);
            m0.z = fmaxf(m0.z, v[u].z);   m1.z = fmaxf(m1.z, v[u+1].z);
            m0.w = fmaxf(m0.w, v[u].w);   m1.w = fmaxf(m1.w, v[u+1].w);
        }
    }

    float4 m;
    m.x = fmaxf(m0.x, m1.x);
    m.y = fmaxf(m0.y, m1.y);
    m.z = fmaxf(m0.z, m1.z);
    m.w = fmaxf(m0.w, m1.w);

    // Write-once output: streaming store, don't pollute L2.
    __stcs(&out[(long long)warp * F_VEC4 + lane], m);
}

extern "C" void kernel_launch(void* const* d_in, const int* in_sizes, int n_in,
                              void* d_out, int out_size)
{
    // Resolve inputs by element count (order-independent):
    //   features : 12800000 f32
    //   indices  : 1600000 int32
    const float4* feat = nullptr;
    const int*    idx  = nullptr;
    for (int i = 0; i < n_in; ++i) {
        if (in_sizes[i] == SZ_FEATURES)     feat = (const float4*)d_in[i];
        else if (in_sizes[i] == SZ_INDICES) idx  = (const int*)d_in[i];
    }
    if (!feat) feat = (const float4*)d_in[1];
    if (!idx)  idx  = (const int*)d_in[2];

    float4* out = (float4*)d_out;

    const int total_threads = NP_POINTS * 32;   // one warp per point
    const int block = 256;
    const int grid = (total_threads + block - 1) / block;  // 6250
    pool_max_kernel<<<grid, block>>>(feat, idx, out);
}

// round 9
// speedup vs baseline: 1.4253x; 1.0066x over previous
#include <cuda_runtime.h>
#include <cstdint>

// PoolingLayer: out[p, f] = max_k features[idx[p,k], f]
// NP=50000, K=32, F=128. features: (100000,128) f32. idx: (50000,32) int32.
//
// 1 warp per output point; lane l owns float4 #l of the row (512B/row, fully
// coalesced). Tuning history: occ93/MLP2 = 45.1us, occ66/MLP4 = 43.8us,
// occ43/MLP8 = 62us. This round: MLP4 at 7 blocks/SM (reg budget 36 via
// single-accumulator pairwise fold) -> occ ~80%.

#define NP_POINTS 50000
#define N_POINTS  100000
#define K_NEIGH   32
#define F_VEC4    32   // 128 floats = 32 float4
#define BATCH     4

#define SZ_FEATURES 12800000   // 100000 * 128 f32
#define SZ_INDICES  1600000    // 50000 * 32

__global__ __launch_bounds__(256, 7)
void pool_max_kernel(const float4* __restrict__ feat,
                     const int* __restrict__ idx,
                     float4* __restrict__ out)
{
    const int gtid = blockIdx.x * blockDim.x + threadIdx.x;
    const int warp = gtid >> 5;
    const int lane = gtid & 31;
    if (warp >= NP_POINTS) return;

    // Coalesced, read-once index load.
    int my_idx = __ldcs(&idx[warp * K_NEIGH + lane]);
    // Clamp: a format surprise becomes rel_err, never an illegal access.
    my_idx = min(max(my_idx, 0), N_POINTS - 1);

    const float NEG_INF = -__int_as_float(0x7f800000);
    float4 m = make_float4(NEG_INF, NEG_INF, NEG_INF, NEG_INF);

    #pragma unroll
    for (int kb = 0; kb < K_NEIGH / BATCH; ++kb) {
        // Phase 1: issue 4 independent gathers (front-batched -> MLP=4).
        float4 v[BATCH];
        #pragma unroll
        for (int u = 0; u < BATCH; ++u) {
            const int j = __shfl_sync(0xffffffffu, my_idx, kb * BATCH + u);
            v[u] = __ldg(&feat[(long long)j * F_VEC4 + lane]);
        }
        // Phase 2: pairwise fold tree (2-deep), then into the accumulator.
        float4 a, b;
        a.x = fmaxf(v[0].x, v[1].x);  b.x = fmaxf(v[2].x, v[3].x);
        a.y = fmaxf(v[0].y, v[1].y);  b.y = fmaxf(v[2].y, v[3].y);
        a.z = fmaxf(v[0].z, v[1].z);  b.z = fmaxf(v[2].z, v[3].z);
        a.w = fmaxf(v[0].w, v[1].w);  b.w = fmaxf(v[2].w, v[3].w);
        m.x = fmaxf(m.x, fmaxf(a.x, b.x));
        m.y = fmaxf(m.y, fmaxf(a.y, b.y));
        m.z = fmaxf(m.z, fmaxf(a.z, b.z));
        m.w = fmaxf(m.w, fmaxf(a.w, b.w));
    }

    // Write-once output: streaming store, don't pollute L2.
    __stcs(&out[(long long)warp * F_VEC4 + lane], m);
}

extern "C" void kernel_launch(void* const* d_in, const int* in_sizes, int n_in,
                              void* d_out, int out_size)
{
    // Resolve inputs by element count (order-independent):
    //   features : 12800000 f32
    //   indices  : 1600000 int32
    const float4* feat = nullptr;
    const int*    idx  = nullptr;
    for (int i = 0; i < n_in; ++i) {
        if (in_sizes[i] == SZ_FEATURES)     feat = (const float4*)d_in[i];
        else if (in_sizes[i] == SZ_INDICES) idx  = (const int*)d_in[i];
    }
    if (!feat) feat = (const float4*)d_in[1];
    if (!idx)  idx  = (const int*)d_in[2];

    float4* out = (float4*)d_out;

    const int total_threads = NP_POINTS * 32;   // one warp per point
    const int block = 256;
    const int grid = (total_threads + block - 1) / block;  // 6250
    pool_max_kernel<<<grid, block>>>(feat, idx, out);
}